// round 12
// baseline (speedup 1.0000x reference)
#include <cuda_runtime.h>
#include <cuda_fp16.h>
#include <stdint.h>

// ---------------------------------------------------------------------------
// Problem dims (fixed by reference setup_inputs)
// ---------------------------------------------------------------------------
#define BATCH   16
#define SEQ     1024
#define DDIM    1024
#define MLPD    500
#define ROWS    (BATCH * SEQ)     // 16384
#define NTOT    (2 * MLPD)        // 1000
#define NPAD    1024
#define NEG_SLOPE 0.01f

// ---------------------------------------------------------------------------
// Device scratch (static __device__ arrays: the sanctioned alloc-free path)
// A is split fp16 hi+lo (captures ~21 mantissa bits); B is single fp16.
// Dominant error = B quantization 2^-11, averaged over K=1024 -> ~3e-4 norm.
// ---------------------------------------------------------------------------
__device__ float   g_scores[ROWS * 4];
__device__ __half  g_a_hi[ROWS * DDIM];      // 32 MB
__device__ __half  g_a_lo[ROWS * DDIM];      // 32 MB
__device__ __half  g_wt[NPAD * DDIM];        // 2 MB  [n][k], rows >=1000 zero

// ---------------------------------------------------------------------------
// Helpers (sm_100-safe: cp.async / ldmatrix / mma.sync only)
// ---------------------------------------------------------------------------
__device__ __forceinline__ uint32_t smem_u32(const void* p) {
    uint32_t a;
    asm("{ .reg .u64 t; cvta.to.shared.u64 t, %1; cvt.u32.u64 %0, t; }"
        : "=r"(a) : "l"(p));
    return a;
}

#define CP_ASYNC16(dst, src) \
    asm volatile("cp.async.cg.shared.global [%0], [%1], 16;" \
                 :: "r"(dst), "l"(src) : "memory")
#define CP_COMMIT()  asm volatile("cp.async.commit_group;" ::: "memory")
#define CP_WAIT1()   asm volatile("cp.async.wait_group 1;" ::: "memory")

#define LDSM_X4(r0, r1, r2, r3, addr) \
    asm volatile("ldmatrix.sync.aligned.m8n8.x4.shared.b16 {%0,%1,%2,%3}, [%4];" \
                 : "=r"(r0), "=r"(r1), "=r"(r2), "=r"(r3) : "r"(addr))

#define MMA_16816(d, a0, a1, a2, a3, b0, b1) \
    asm volatile("mma.sync.aligned.m16n8k16.row.col.f32.f16.f16.f32 " \
                 "{%0,%1,%2,%3}, {%4,%5,%6,%7}, {%8,%9}, {%0,%1,%2,%3};" \
                 : "+f"((d)[0]), "+f"((d)[1]), "+f"((d)[2]), "+f"((d)[3]) \
                 : "r"(a0), "r"(a1), "r"(a2), "r"(a3), "r"(b0), "r"(b1))

// ---------------------------------------------------------------------------
// Kernel 0: zero scores scratch
// ---------------------------------------------------------------------------
__global__ void zero_scores_kernel() {
    int idx = blockIdx.x * blockDim.x + threadIdx.x;
    if (idx < ROWS * 4) g_scores[idx] = 0.0f;
}

// ---------------------------------------------------------------------------
// Kernel 1: split hidden fp32 -> fp16 hi/lo
// ---------------------------------------------------------------------------
__global__ __launch_bounds__(256)
void convert_a_kernel(const float* __restrict__ A) {
    int i = blockIdx.x * blockDim.x + threadIdx.x;        // float4 index
    float4 v = reinterpret_cast<const float4*>(A)[i];
    __half h0 = __float2half(v.x);
    __half h1 = __float2half(v.y);
    __half h2 = __float2half(v.z);
    __half h3 = __float2half(v.w);
    __half l0 = __float2half(v.x - __half2float(h0));
    __half l1 = __float2half(v.y - __half2float(h1));
    __half l2 = __float2half(v.z - __half2float(h2));
    __half l3 = __float2half(v.w - __half2float(h3));
    __half2* H = reinterpret_cast<__half2*>(g_a_hi);
    __half2* L = reinterpret_cast<__half2*>(g_a_lo);
    __half2 p0; p0.x = h0; p0.y = h1;
    __half2 p1; p1.x = h2; p1.y = h3;
    __half2 q0; q0.x = l0; q0.y = l1;
    __half2 q1; q1.x = l2; q1.y = l3;
    H[2 * i + 0] = p0;  H[2 * i + 1] = p1;
    L[2 * i + 0] = q0;  L[2 * i + 1] = q1;
}

// ---------------------------------------------------------------------------
// Kernel 2: transpose W_dep|W_head fp32 -> fp16 [NPAD][DDIM]
// ---------------------------------------------------------------------------
__global__ __launch_bounds__(256)
void transpose_w_kernel(const float* __restrict__ Wd, const float* __restrict__ Wh) {
    __shared__ float tile[32][33];
    const int n0 = blockIdx.x * 32;
    const int k0 = blockIdx.y * 32;
    const int tx = threadIdx.x, ty = threadIdx.y;    // 32 x 8

    #pragma unroll
    for (int i = 0; i < 4; i++) {
        int k = k0 + ty + i * 8;
        int n = n0 + tx;
        float val = 0.0f;
        if (n < MLPD)       val = Wd[(size_t)k * MLPD + n];
        else if (n < NTOT)  val = Wh[(size_t)k * MLPD + (n - MLPD)];
        tile[ty + i * 8][tx] = val;              // tile[kk][nn]
    }
    __syncthreads();
    #pragma unroll
    for (int i = 0; i < 4; i++) {
        int n = n0 + ty + i * 8;
        int k = k0 + tx;
        g_wt[(size_t)n * DDIM + k] = __float2half(tile[tx][ty + i * 8]);
    }
}

// ---------------------------------------------------------------------------
// Kernel 3: fp16-split mma.sync GEMM + fused epilogue
// Grid (8, 128), 256 threads (8 warps: 4 m x 2 n), 128x128x32 CTA tile.
// Warp tile 32x64 (optimal LDSM reuse: A*2 + B*4 = 32KB/ks vs 40KB for 2x4).
// 3-stage cp.async pipeline. 2 MMA passes: a_hi*b + a_lo*b.
// ---------------------------------------------------------------------------
#define BM 128
#define BN 128
#define BK 32
#define STAGES 3
#define MAT_BYTES  (BM * BK * 2)      // 8192
#define STAGE_B    (3 * MAT_BYTES)    // 24576
#define AHI 0
#define ALO MAT_BYTES
#define BOF (2 * MAT_BYTES)
#define DYN_SMEM   (STAGES * STAGE_B) // 73728

__global__ __launch_bounds__(256)
void gemm_mma_kernel(const float* __restrict__ bdep, const float* __restrict__ bhead,
                     const float* __restrict__ Wc) {
    extern __shared__ char smem[];
    const uint32_t sb = smem_u32(smem);

    const int tid    = threadIdx.x;
    const int lane   = tid & 31;
    const int wid    = tid >> 5;
    const int warp_m = wid & 3;        // 0..3  (32-row group)
    const int warp_n = wid >> 2;       // 0..1  (64-col group)
    const int row0   = blockIdx.y * BM;
    const int n0     = blockIdx.x * BN;

    // per-lane ldmatrix geometry
    const int a_mlane = (lane & 15);          // row within 16-row A tile
    const int a_kh    = lane >> 4;            // k-half (0/1)
    const int b_nlane = (lane & 7) + ((lane >> 4) << 3);  // row within 16-row B pair
    const int b_kh    = (lane >> 3) & 1;

    float acc[2][8][4];
    #pragma unroll
    for (int i = 0; i < 2; i++)
        #pragma unroll
        for (int j = 0; j < 8; j++)
            #pragma unroll
            for (int e = 0; e < 4; e++) acc[i][j][e] = 0.0f;

    // ---- stage loader: 2 chunks per matrix per thread, 16B cp.async ----
    auto load_stage = [&](int stage, int kt) {
        const uint32_t s0 = sb + stage * STAGE_B;
        #pragma unroll
        for (int i = 0; i < 2; i++) {
            int idx = tid + i * 256;          // 0..511
            int m  = idx >> 2;                // row 0..127
            int kc = idx & 3;                 // 16B chunk 0..3
            uint32_t doff = (uint32_t)(m * 64 + ((kc ^ (m & 3)) << 4));
            size_t gsrc  = (size_t)(row0 + m) * DDIM + kt + kc * 8;
            size_t gsrcB = (size_t)(n0 + m) * DDIM + kt + kc * 8;
            CP_ASYNC16(s0 + AHI + doff, (const void*)(g_a_hi + gsrc));
            CP_ASYNC16(s0 + ALO + doff, (const void*)(g_a_lo + gsrc));
            CP_ASYNC16(s0 + BOF + doff, (const void*)(g_wt + gsrcB));
        }
    };

    // prologue: stages 0 and 1
    load_stage(0, 0);
    CP_COMMIT();
    load_stage(1, BK);
    CP_COMMIT();

    const int NKC = DDIM / BK;   // 32
    for (int kc = 0; kc < NKC; kc++) {
        CP_WAIT1();
        __syncthreads();

        // issue loads for kc+2 into the stage freed last iteration
        if (kc + 2 < NKC) load_stage((kc + 2) % STAGES, (kc + 2) * BK);
        CP_COMMIT();

        const uint32_t s0 = sb + (kc % STAGES) * STAGE_B;

        #pragma unroll
        for (int ks = 0; ks < 2; ks++) {
            uint32_t ah[2][4], al[2][4], bh[16];
            // A fragments (2 m-tiles), hi and lo
            #pragma unroll
            for (int mt = 0; mt < 2; mt++) {
                int m = warp_m * 32 + mt * 16 + a_mlane;
                uint32_t off = (uint32_t)(m * 64 + (((ks * 2 + a_kh) ^ (m & 3)) << 4));
                LDSM_X4(ah[mt][0], ah[mt][1], ah[mt][2], ah[mt][3], s0 + AHI + off);
                LDSM_X4(al[mt][0], al[mt][1], al[mt][2], al[mt][3], s0 + ALO + off);
            }
            // B fragments (4 n-tile pairs -> 8 n-tiles)
            #pragma unroll
            for (int np = 0; np < 4; np++) {
                int n = warp_n * 64 + np * 16 + b_nlane;
                uint32_t off = (uint32_t)(n * 64 + (((ks * 2 + b_kh) ^ (n & 3)) << 4));
                LDSM_X4(bh[np * 4 + 0], bh[np * 4 + 1], bh[np * 4 + 2], bh[np * 4 + 3],
                        s0 + BOF + off);
            }
            // 2 passes: a_hi*b + a_lo*b
            #pragma unroll
            for (int mt = 0; mt < 2; mt++) {
                #pragma unroll
                for (int nt = 0; nt < 8; nt++) {
                    int bi = (nt >> 1) * 4 + (nt & 1) * 2;
                    MMA_16816(acc[mt][nt], ah[mt][0], ah[mt][1], ah[mt][2], ah[mt][3],
                              bh[bi], bh[bi + 1]);
                    MMA_16816(acc[mt][nt], al[mt][0], al[mt][1], al[mt][2], al[mt][3],
                              bh[bi], bh[bi + 1]);
                }
            }
        }
    }

    // ---- epilogue: bias + leaky + Wc contraction, quad reduce, atomicAdd ----
    float part[2][2][4];
    #pragma unroll
    for (int mt = 0; mt < 2; mt++)
        #pragma unroll
        for (int h = 0; h < 2; h++)
            #pragma unroll
            for (int s = 0; s < 4; s++) part[mt][h][s] = 0.0f;

    #pragma unroll
    for (int nt = 0; nt < 8; nt++) {
        #pragma unroll
        for (int e = 0; e < 4; e++) {
            int n = n0 + warp_n * 64 + nt * 8 + (lane & 3) * 2 + (e & 1);
            if (n >= NTOT) continue;
            float bias = (n < MLPD) ? __ldg(bdep + n) : __ldg(bhead + n - MLPD);
            float w0 = __ldg(Wc + 2 * n);
            float w1 = __ldg(Wc + 2 * n + 1);
            int s = (n < MLPD) ? 0 : 2;
            int half = e >> 1;
            #pragma unroll
            for (int mt = 0; mt < 2; mt++) {
                float v = acc[mt][nt][e] + bias;
                v = (v > 0.0f) ? v : NEG_SLOPE * v;
                part[mt][half][s + 0] += v * w0;
                part[mt][half][s + 1] += v * w1;
            }
        }
    }

    // reduce across the 4 lanes of each quad (they share the same rows)
    #pragma unroll
    for (int mt = 0; mt < 2; mt++)
        #pragma unroll
        for (int h = 0; h < 2; h++)
            #pragma unroll
            for (int s = 0; s < 4; s++) {
                float v = part[mt][h][s];
                v += __shfl_xor_sync(0xffffffffu, v, 1);
                v += __shfl_xor_sync(0xffffffffu, v, 2);
                part[mt][h][s] = v;
            }

    if ((lane & 3) == 0) {
        #pragma unroll
        for (int mt = 0; mt < 2; mt++)
            #pragma unroll
            for (int h = 0; h < 2; h++) {
                int row = row0 + warp_m * 32 + mt * 16 + (lane >> 2) + h * 8;
                #pragma unroll
                for (int s = 0; s < 4; s++)
                    atomicAdd(&g_scores[row * 4 + s], part[mt][h][s]);
            }
    }
}

// ---------------------------------------------------------------------------
// Kernel 4: broadcast pairwise add -> out[b,i,j,c]
// ---------------------------------------------------------------------------
__global__ __launch_bounds__(256)
void broadcast_add_kernel(const float* __restrict__ bc, float* __restrict__ out) {
    __shared__ float hs[SEQ * 2];
    const int row = blockIdx.x;
    const int b   = row >> 10;
    const int tid = threadIdx.x;

    for (int j = tid; j < SEQ; j += 256) {
        int hr = (b << 10) + j;
        hs[2 * j + 0] = g_scores[hr * 4 + 2];
        hs[2 * j + 1] = g_scores[hr * 4 + 3];
    }
    __syncthreads();

    const float d0 = g_scores[row * 4 + 0] + bc[0];
    const float d1 = g_scores[row * 4 + 1] + bc[1];

    float4* o = reinterpret_cast<float4*>(out + (size_t)row * (SEQ * 2));
    for (int f = tid; f < SEQ * 2 / 4; f += 256) {
        int j = 2 * f;
        float4 v;
        v.x = d0 + hs[2 * j + 0];
        v.y = d1 + hs[2 * j + 1];
        v.z = d0 + hs[2 * j + 2];
        v.w = d1 + hs[2 * j + 3];
        o[f] = v;
    }
}

// ---------------------------------------------------------------------------
// Launch
// ---------------------------------------------------------------------------
extern "C" void kernel_launch(void* const* d_in, const int* in_sizes, int n_in,
                              void* d_out, int out_size)
{
    (void)in_sizes; (void)n_in; (void)out_size;
    const float* hidden = (const float*)d_in[0];
    const float* Wd     = (const float*)d_in[1];
    const float* bd     = (const float*)d_in[2];
    const float* Wh     = (const float*)d_in[3];
    const float* bh     = (const float*)d_in[4];
    const float* Wc     = (const float*)d_in[5];
    const float* bc     = (const float*)d_in[6];
    float* out          = (float*)d_out;

    cudaFuncSetAttribute(gemm_mma_kernel,
                         cudaFuncAttributeMaxDynamicSharedMemorySize, DYN_SMEM);

    zero_scores_kernel<<<(ROWS * 4 + 255) / 256, 256>>>();
    convert_a_kernel<<<ROWS * DDIM / 4 / 256, 256>>>(hidden);
    transpose_w_kernel<<<dim3(NPAD / 32, DDIM / 32), dim3(32, 8)>>>(Wd, Wh);
    gemm_mma_kernel<<<dim3(NPAD / BN, ROWS / BM), 256, DYN_SMEM>>>(bd, bh, Wc);
    broadcast_add_kernel<<<ROWS, 256>>>(bc, out);
}

// round 13
// speedup vs baseline: 1.0021x; 1.0021x over previous
#include <cuda_runtime.h>
#include <cuda_fp16.h>
#include <stdint.h>

// ---------------------------------------------------------------------------
// Problem dims (fixed by reference setup_inputs)
// ---------------------------------------------------------------------------
#define BATCH   16
#define SEQ     1024
#define DDIM    1024
#define MLPD    500
#define ROWS    (BATCH * SEQ)     // 16384
#define NTOT    (2 * MLPD)        // 1000
#define NPAD    1024
#define NEG_SLOPE 0.01f

// ---------------------------------------------------------------------------
// Device scratch (static __device__ arrays: the sanctioned alloc-free path)
// A is split fp16 hi+lo (captures ~21 mantissa bits); B is single fp16.
// Dominant error = B quantization 2^-11, averaged over K=1024 -> ~3e-4 norm.
// ---------------------------------------------------------------------------
__device__ float   g_scores[ROWS * 4];
__device__ __half  g_a_hi[ROWS * DDIM];      // 32 MB
__device__ __half  g_a_lo[ROWS * DDIM];      // 32 MB
__device__ __half  g_wt[NPAD * DDIM];        // 2 MB  [n][k], rows >=1000 zero

// ---------------------------------------------------------------------------
// Helpers (sm_100-safe: cp.async / ldmatrix / mma.sync only)
// ---------------------------------------------------------------------------
__device__ __forceinline__ uint32_t smem_u32(const void* p) {
    uint32_t a;
    asm("{ .reg .u64 t; cvta.to.shared.u64 t, %1; cvt.u32.u64 %0, t; }"
        : "=r"(a) : "l"(p));
    return a;
}

#define CP_ASYNC16(dst, src) \
    asm volatile("cp.async.cg.shared.global [%0], [%1], 16;" \
                 :: "r"(dst), "l"(src) : "memory")
#define CP_COMMIT()  asm volatile("cp.async.commit_group;" ::: "memory")
#define CP_WAIT1()   asm volatile("cp.async.wait_group 1;" ::: "memory")

#define LDSM_X4(r0, r1, r2, r3, addr) \
    asm volatile("ldmatrix.sync.aligned.m8n8.x4.shared.b16 {%0,%1,%2,%3}, [%4];" \
                 : "=r"(r0), "=r"(r1), "=r"(r2), "=r"(r3) : "r"(addr))

#define MMA_16816(d, a0, a1, a2, a3, b0, b1) \
    asm volatile("mma.sync.aligned.m16n8k16.row.col.f32.f16.f16.f32 " \
                 "{%0,%1,%2,%3}, {%4,%5,%6,%7}, {%8,%9}, {%0,%1,%2,%3};" \
                 : "+f"((d)[0]), "+f"((d)[1]), "+f"((d)[2]), "+f"((d)[3]) \
                 : "r"(a0), "r"(a1), "r"(a2), "r"(a3), "r"(b0), "r"(b1))

// ---------------------------------------------------------------------------
// Kernel 0: zero scores scratch
// ---------------------------------------------------------------------------
__global__ void zero_scores_kernel() {
    int idx = blockIdx.x * blockDim.x + threadIdx.x;
    if (idx < ROWS * 4) g_scores[idx] = 0.0f;
}

// ---------------------------------------------------------------------------
// Kernel 1: split hidden fp32 -> fp16 hi/lo
// ---------------------------------------------------------------------------
__global__ __launch_bounds__(256)
void convert_a_kernel(const float* __restrict__ A) {
    int i = blockIdx.x * blockDim.x + threadIdx.x;        // float4 index
    float4 v = reinterpret_cast<const float4*>(A)[i];
    __half h0 = __float2half(v.x);
    __half h1 = __float2half(v.y);
    __half h2 = __float2half(v.z);
    __half h3 = __float2half(v.w);
    __half l0 = __float2half(v.x - __half2float(h0));
    __half l1 = __float2half(v.y - __half2float(h1));
    __half l2 = __float2half(v.z - __half2float(h2));
    __half l3 = __float2half(v.w - __half2float(h3));
    __half2* H = reinterpret_cast<__half2*>(g_a_hi);
    __half2* L = reinterpret_cast<__half2*>(g_a_lo);
    __half2 p0; p0.x = h0; p0.y = h1;
    __half2 p1; p1.x = h2; p1.y = h3;
    __half2 q0; q0.x = l0; q0.y = l1;
    __half2 q1; q1.x = l2; q1.y = l3;
    H[2 * i + 0] = p0;  H[2 * i + 1] = p1;
    L[2 * i + 0] = q0;  L[2 * i + 1] = q1;
}

// ---------------------------------------------------------------------------
// Kernel 2: transpose W_dep|W_head fp32 -> fp16 [NPAD][DDIM]
// ---------------------------------------------------------------------------
__global__ __launch_bounds__(256)
void transpose_w_kernel(const float* __restrict__ Wd, const float* __restrict__ Wh) {
    __shared__ float tile[32][33];
    const int n0 = blockIdx.x * 32;
    const int k0 = blockIdx.y * 32;
    const int tx = threadIdx.x, ty = threadIdx.y;    // 32 x 8

    #pragma unroll
    for (int i = 0; i < 4; i++) {
        int k = k0 + ty + i * 8;
        int n = n0 + tx;
        float val = 0.0f;
        if (n < MLPD)       val = Wd[(size_t)k * MLPD + n];
        else if (n < NTOT)  val = Wh[(size_t)k * MLPD + (n - MLPD)];
        tile[ty + i * 8][tx] = val;              // tile[kk][nn]
    }
    __syncthreads();
    #pragma unroll
    for (int i = 0; i < 4; i++) {
        int n = n0 + ty + i * 8;
        int k = k0 + tx;
        g_wt[(size_t)n * DDIM + k] = __float2half(tile[tx][ty + i * 8]);
    }
}

// ---------------------------------------------------------------------------
// Kernel 3: fp16-split mma.sync GEMM + fused epilogue
// Grid (8, 128), 256 threads (8 warps: 4 m x 2 n), 128x128x32 CTA tile.
// Warp tile 32x64 (optimal LDSM reuse: A*2 + B*4 = 32KB/ks vs 40KB for 2x4).
// 3-stage cp.async pipeline. 2 MMA passes: a_hi*b + a_lo*b.
// ---------------------------------------------------------------------------
#define BM 128
#define BN 128
#define BK 32
#define STAGES 3
#define MAT_BYTES  (BM * BK * 2)      // 8192
#define STAGE_B    (3 * MAT_BYTES)    // 24576
#define AHI 0
#define ALO MAT_BYTES
#define BOF (2 * MAT_BYTES)
#define DYN_SMEM   (STAGES * STAGE_B) // 73728

__global__ __launch_bounds__(256)
void gemm_mma_kernel(const float* __restrict__ bdep, const float* __restrict__ bhead,
                     const float* __restrict__ Wc) {
    extern __shared__ char smem[];
    const uint32_t sb = smem_u32(smem);

    const int tid    = threadIdx.x;
    const int lane   = tid & 31;
    const int wid    = tid >> 5;
    const int warp_m = wid & 3;        // 0..3  (32-row group)
    const int warp_n = wid >> 2;       // 0..1  (64-col group)
    const int row0   = blockIdx.y * BM;
    const int n0     = blockIdx.x * BN;

    // per-lane ldmatrix geometry
    const int a_mlane = (lane & 15);          // row within 16-row A tile
    const int a_kh    = lane >> 4;            // k-half (0/1)
    const int b_nlane = (lane & 7) + ((lane >> 4) << 3);  // row within 16-row B pair
    const int b_kh    = (lane >> 3) & 1;

    float acc[2][8][4];
    #pragma unroll
    for (int i = 0; i < 2; i++)
        #pragma unroll
        for (int j = 0; j < 8; j++)
            #pragma unroll
            for (int e = 0; e < 4; e++) acc[i][j][e] = 0.0f;

    // ---- stage loader: 2 chunks per matrix per thread, 16B cp.async ----
    auto load_stage = [&](int stage, int kt) {
        const uint32_t s0 = sb + stage * STAGE_B;
        #pragma unroll
        for (int i = 0; i < 2; i++) {
            int idx = tid + i * 256;          // 0..511
            int m  = idx >> 2;                // row 0..127
            int kc = idx & 3;                 // 16B chunk 0..3
            uint32_t doff = (uint32_t)(m * 64 + ((kc ^ (m & 3)) << 4));
            size_t gsrc  = (size_t)(row0 + m) * DDIM + kt + kc * 8;
            size_t gsrcB = (size_t)(n0 + m) * DDIM + kt + kc * 8;
            CP_ASYNC16(s0 + AHI + doff, (const void*)(g_a_hi + gsrc));
            CP_ASYNC16(s0 + ALO + doff, (const void*)(g_a_lo + gsrc));
            CP_ASYNC16(s0 + BOF + doff, (const void*)(g_wt + gsrcB));
        }
    };

    // prologue: stages 0 and 1
    load_stage(0, 0);
    CP_COMMIT();
    load_stage(1, BK);
    CP_COMMIT();

    const int NKC = DDIM / BK;   // 32
    for (int kc = 0; kc < NKC; kc++) {
        CP_WAIT1();
        __syncthreads();

        // issue loads for kc+2 into the stage freed last iteration
        if (kc + 2 < NKC) load_stage((kc + 2) % STAGES, (kc + 2) * BK);
        CP_COMMIT();

        const uint32_t s0 = sb + (kc % STAGES) * STAGE_B;

        #pragma unroll
        for (int ks = 0; ks < 2; ks++) {
            uint32_t ah[2][4], al[2][4], bh[16];
            // A fragments (2 m-tiles), hi and lo
            #pragma unroll
            for (int mt = 0; mt < 2; mt++) {
                int m = warp_m * 32 + mt * 16 + a_mlane;
                uint32_t off = (uint32_t)(m * 64 + (((ks * 2 + a_kh) ^ (m & 3)) << 4));
                LDSM_X4(ah[mt][0], ah[mt][1], ah[mt][2], ah[mt][3], s0 + AHI + off);
                LDSM_X4(al[mt][0], al[mt][1], al[mt][2], al[mt][3], s0 + ALO + off);
            }
            // B fragments (4 n-tile pairs -> 8 n-tiles)
            #pragma unroll
            for (int np = 0; np < 4; np++) {
                int n = warp_n * 64 + np * 16 + b_nlane;
                uint32_t off = (uint32_t)(n * 64 + (((ks * 2 + b_kh) ^ (n & 3)) << 4));
                LDSM_X4(bh[np * 4 + 0], bh[np * 4 + 1], bh[np * 4 + 2], bh[np * 4 + 3],
                        s0 + BOF + off);
            }
            // 2 passes: a_hi*b + a_lo*b
            #pragma unroll
            for (int mt = 0; mt < 2; mt++) {
                #pragma unroll
                for (int nt = 0; nt < 8; nt++) {
                    int bi = (nt >> 1) * 4 + (nt & 1) * 2;
                    MMA_16816(acc[mt][nt], ah[mt][0], ah[mt][1], ah[mt][2], ah[mt][3],
                              bh[bi], bh[bi + 1]);
                    MMA_16816(acc[mt][nt], al[mt][0], al[mt][1], al[mt][2], al[mt][3],
                              bh[bi], bh[bi + 1]);
                }
            }
        }
    }

    // ---- epilogue: bias + leaky + Wc contraction, quad reduce, atomicAdd ----
    float part[2][2][4];
    #pragma unroll
    for (int mt = 0; mt < 2; mt++)
        #pragma unroll
        for (int h = 0; h < 2; h++)
            #pragma unroll
            for (int s = 0; s < 4; s++) part[mt][h][s] = 0.0f;

    #pragma unroll
    for (int nt = 0; nt < 8; nt++) {
        #pragma unroll
        for (int e = 0; e < 4; e++) {
            int n = n0 + warp_n * 64 + nt * 8 + (lane & 3) * 2 + (e & 1);
            if (n >= NTOT) continue;
            float bias = (n < MLPD) ? __ldg(bdep + n) : __ldg(bhead + n - MLPD);
            float w0 = __ldg(Wc + 2 * n);
            float w1 = __ldg(Wc + 2 * n + 1);
            int s = (n < MLPD) ? 0 : 2;
            int half = e >> 1;
            #pragma unroll
            for (int mt = 0; mt < 2; mt++) {
                float v = acc[mt][nt][e] + bias;
                v = (v > 0.0f) ? v : NEG_SLOPE * v;
                part[mt][half][s + 0] += v * w0;
                part[mt][half][s + 1] += v * w1;
            }
        }
    }

    // reduce across the 4 lanes of each quad (they share the same rows)
    #pragma unroll
    for (int mt = 0; mt < 2; mt++)
        #pragma unroll
        for (int h = 0; h < 2; h++)
            #pragma unroll
            for (int s = 0; s < 4; s++) {
                float v = part[mt][h][s];
                v += __shfl_xor_sync(0xffffffffu, v, 1);
                v += __shfl_xor_sync(0xffffffffu, v, 2);
                part[mt][h][s] = v;
            }

    if ((lane & 3) == 0) {
        #pragma unroll
        for (int mt = 0; mt < 2; mt++)
            #pragma unroll
            for (int h = 0; h < 2; h++) {
                int row = row0 + warp_m * 32 + mt * 16 + (lane >> 2) + h * 8;
                #pragma unroll
                for (int s = 0; s < 4; s++)
                    atomicAdd(&g_scores[row * 4 + s], part[mt][h][s]);
            }
    }
}

// ---------------------------------------------------------------------------
// Kernel 4: broadcast pairwise add -> out[b,i,j,c]
// ---------------------------------------------------------------------------
__global__ __launch_bounds__(256)
void broadcast_add_kernel(const float* __restrict__ bc, float* __restrict__ out) {
    __shared__ float hs[SEQ * 2];
    const int row = blockIdx.x;
    const int b   = row >> 10;
    const int tid = threadIdx.x;

    for (int j = tid; j < SEQ; j += 256) {
        int hr = (b << 10) + j;
        hs[2 * j + 0] = g_scores[hr * 4 + 2];
        hs[2 * j + 1] = g_scores[hr * 4 + 3];
    }
    __syncthreads();

    const float d0 = g_scores[row * 4 + 0] + bc[0];
    const float d1 = g_scores[row * 4 + 1] + bc[1];

    float4* o = reinterpret_cast<float4*>(out + (size_t)row * (SEQ * 2));
    for (int f = tid; f < SEQ * 2 / 4; f += 256) {
        int j = 2 * f;
        float4 v;
        v.x = d0 + hs[2 * j + 0];
        v.y = d1 + hs[2 * j + 1];
        v.z = d0 + hs[2 * j + 2];
        v.w = d1 + hs[2 * j + 3];
        o[f] = v;
    }
}

// ---------------------------------------------------------------------------
// Launch
// ---------------------------------------------------------------------------
extern "C" void kernel_launch(void* const* d_in, const int* in_sizes, int n_in,
                              void* d_out, int out_size)
{
    (void)in_sizes; (void)n_in; (void)out_size;
    const float* hidden = (const float*)d_in[0];
    const float* Wd     = (const float*)d_in[1];
    const float* bd     = (const float*)d_in[2];
    const float* Wh     = (const float*)d_in[3];
    const float* bh     = (const float*)d_in[4];
    const float* Wc     = (const float*)d_in[5];
    const float* bc     = (const float*)d_in[6];
    float* out          = (float*)d_out;

    cudaFuncSetAttribute(gemm_mma_kernel,
                         cudaFuncAttributeMaxDynamicSharedMemorySize, DYN_SMEM);

    zero_scores_kernel<<<(ROWS * 4 + 255) / 256, 256>>>();
    convert_a_kernel<<<ROWS * DDIM / 4 / 256, 256>>>(hidden);
    transpose_w_kernel<<<dim3(NPAD / 32, DDIM / 32), dim3(32, 8)>>>(Wd, Wh);
    gemm_mma_kernel<<<dim3(NPAD / BN, ROWS / BM), 256, DYN_SMEM>>>(bd, bh, Wc);
    broadcast_add_kernel<<<ROWS, 256>>>(bc, out);
}

// round 14
// speedup vs baseline: 1.1515x; 1.1490x over previous
#include <cuda_runtime.h>
#include <cuda_fp16.h>
#include <stdint.h>

// ---------------------------------------------------------------------------
// Problem dims (fixed by reference setup_inputs)
// ---------------------------------------------------------------------------
#define BATCH   16
#define SEQ     1024
#define DDIM    1024
#define MLPD    500
#define ROWS    (BATCH * SEQ)     // 16384
#define NTOT    (2 * MLPD)        // 1000
#define NPAD    1024
#define NEG_SLOPE 0.01f

// ---------------------------------------------------------------------------
// Device scratch. Plain fp16 A and B: measured B-only quantization error was
// 1.94e-4; adding independent A quantization gives ~sqrt(2)*1.94e-4 ~ 2.8e-4,
// a 3.6x margin under the 1e-3 threshold.
// ---------------------------------------------------------------------------
__device__ float   g_scores[ROWS * 4];
__device__ __half  g_a[ROWS * DDIM];         // 32 MB
__device__ __half  g_wt[NPAD * DDIM];        // 2 MB  [n][k], rows >=1000 zero

// ---------------------------------------------------------------------------
// Helpers (sm_100-safe: cp.async / ldmatrix / mma.sync only)
// ---------------------------------------------------------------------------
__device__ __forceinline__ uint32_t smem_u32(const void* p) {
    uint32_t a;
    asm("{ .reg .u64 t; cvta.to.shared.u64 t, %1; cvt.u32.u64 %0, t; }"
        : "=r"(a) : "l"(p));
    return a;
}

#define CP_ASYNC16(dst, src) \
    asm volatile("cp.async.cg.shared.global [%0], [%1], 16;" \
                 :: "r"(dst), "l"(src) : "memory")
#define CP_COMMIT()  asm volatile("cp.async.commit_group;" ::: "memory")
#define CP_WAIT1()   asm volatile("cp.async.wait_group 1;" ::: "memory")

#define LDSM_X4(r0, r1, r2, r3, addr) \
    asm volatile("ldmatrix.sync.aligned.m8n8.x4.shared.b16 {%0,%1,%2,%3}, [%4];" \
                 : "=r"(r0), "=r"(r1), "=r"(r2), "=r"(r3) : "r"(addr))

#define MMA_16816(d, a0, a1, a2, a3, b0, b1) \
    asm volatile("mma.sync.aligned.m16n8k16.row.col.f32.f16.f16.f32 " \
                 "{%0,%1,%2,%3}, {%4,%5,%6,%7}, {%8,%9}, {%0,%1,%2,%3};" \
                 : "+f"((d)[0]), "+f"((d)[1]), "+f"((d)[2]), "+f"((d)[3]) \
                 : "r"(a0), "r"(a1), "r"(a2), "r"(a3), "r"(b0), "r"(b1))

// ---------------------------------------------------------------------------
// Kernel 0: zero scores scratch
// ---------------------------------------------------------------------------
__global__ void zero_scores_kernel() {
    int idx = blockIdx.x * blockDim.x + threadIdx.x;
    if (idx < ROWS * 4) g_scores[idx] = 0.0f;
}

// ---------------------------------------------------------------------------
// Kernel 1: convert hidden fp32 -> fp16
// ---------------------------------------------------------------------------
__global__ __launch_bounds__(256)
void convert_a_kernel(const float* __restrict__ A) {
    int i = blockIdx.x * blockDim.x + threadIdx.x;        // float4 index
    float4 v = reinterpret_cast<const float4*>(A)[i];
    __half2 p0; p0.x = __float2half(v.x); p0.y = __float2half(v.y);
    __half2 p1; p1.x = __float2half(v.z); p1.y = __float2half(v.w);
    __half2* H = reinterpret_cast<__half2*>(g_a);
    H[2 * i + 0] = p0;  H[2 * i + 1] = p1;
}

// ---------------------------------------------------------------------------
// Kernel 2: transpose W_dep|W_head fp32 -> fp16 [NPAD][DDIM]
// ---------------------------------------------------------------------------
__global__ __launch_bounds__(256)
void transpose_w_kernel(const float* __restrict__ Wd, const float* __restrict__ Wh) {
    __shared__ float tile[32][33];
    const int n0 = blockIdx.x * 32;
    const int k0 = blockIdx.y * 32;
    const int tx = threadIdx.x, ty = threadIdx.y;    // 32 x 8

    #pragma unroll
    for (int i = 0; i < 4; i++) {
        int k = k0 + ty + i * 8;
        int n = n0 + tx;
        float val = 0.0f;
        if (n < MLPD)       val = Wd[(size_t)k * MLPD + n];
        else if (n < NTOT)  val = Wh[(size_t)k * MLPD + (n - MLPD)];
        tile[ty + i * 8][tx] = val;              // tile[kk][nn]
    }
    __syncthreads();
    #pragma unroll
    for (int i = 0; i < 4; i++) {
        int n = n0 + ty + i * 8;
        int k = k0 + tx;
        g_wt[(size_t)n * DDIM + k] = __float2half(tile[tx][ty + i * 8]);
    }
}

// ---------------------------------------------------------------------------
// Kernel 3: fp16 mma.sync GEMM + fused epilogue
// Grid (8, 128), 256 threads (8 warps: 4 m x 2 n), 128x128x32 CTA tile.
// Warp tile 32x64. 3-stage cp.async pipeline. Single MMA pass.
// ---------------------------------------------------------------------------
#define BM 128
#define BN 128
#define BK 32
#define STAGES 3
#define MAT_BYTES  (BM * BK * 2)      // 8192
#define STAGE_B    (2 * MAT_BYTES)    // 16384
#define AOF 0
#define BOF MAT_BYTES
#define DYN_SMEM   (STAGES * STAGE_B) // 49152

__global__ __launch_bounds__(256)
void gemm_mma_kernel(const float* __restrict__ bdep, const float* __restrict__ bhead,
                     const float* __restrict__ Wc) {
    extern __shared__ char smem[];
    const uint32_t sb = smem_u32(smem);

    const int tid    = threadIdx.x;
    const int lane   = tid & 31;
    const int wid    = tid >> 5;
    const int warp_m = wid & 3;        // 0..3  (32-row group)
    const int warp_n = wid >> 2;       // 0..1  (64-col group)
    const int row0   = blockIdx.y * BM;
    const int n0     = blockIdx.x * BN;

    // per-lane ldmatrix geometry
    const int a_mlane = (lane & 15);          // row within 16-row A tile
    const int a_kh    = lane >> 4;            // k-half (0/1)
    const int b_nlane = (lane & 7) + ((lane >> 4) << 3);  // row within 16-row B pair
    const int b_kh    = (lane >> 3) & 1;

    float acc[2][8][4];
    #pragma unroll
    for (int i = 0; i < 2; i++)
        #pragma unroll
        for (int j = 0; j < 8; j++)
            #pragma unroll
            for (int e = 0; e < 4; e++) acc[i][j][e] = 0.0f;

    // ---- stage loader: 2 x 16B chunks per matrix per thread ----
    auto load_stage = [&](int stage, int kt) {
        const uint32_t s0 = sb + stage * STAGE_B;
        #pragma unroll
        for (int i = 0; i < 2; i++) {
            int idx = tid + i * 256;          // 0..511
            int m  = idx >> 2;                // row 0..127
            int kc = idx & 3;                 // 16B chunk 0..3
            uint32_t doff = (uint32_t)(m * 64 + ((kc ^ (m & 3)) << 4));
            size_t gsrc  = (size_t)(row0 + m) * DDIM + kt + kc * 8;
            size_t gsrcB = (size_t)(n0 + m) * DDIM + kt + kc * 8;
            CP_ASYNC16(s0 + AOF + doff, (const void*)(g_a + gsrc));
            CP_ASYNC16(s0 + BOF + doff, (const void*)(g_wt + gsrcB));
        }
    };

    // prologue: stages 0 and 1
    load_stage(0, 0);
    CP_COMMIT();
    load_stage(1, BK);
    CP_COMMIT();

    const int NKC = DDIM / BK;   // 32
    for (int kc = 0; kc < NKC; kc++) {
        CP_WAIT1();
        __syncthreads();

        // issue loads for kc+2 into the stage freed last iteration
        if (kc + 2 < NKC) load_stage((kc + 2) % STAGES, (kc + 2) * BK);
        CP_COMMIT();

        const uint32_t s0 = sb + (kc % STAGES) * STAGE_B;

        #pragma unroll
        for (int ks = 0; ks < 2; ks++) {
            uint32_t ah[2][4], bh[16];
            // A fragments (2 m-tiles)
            #pragma unroll
            for (int mt = 0; mt < 2; mt++) {
                int m = warp_m * 32 + mt * 16 + a_mlane;
                uint32_t off = (uint32_t)(m * 64 + (((ks * 2 + a_kh) ^ (m & 3)) << 4));
                LDSM_X4(ah[mt][0], ah[mt][1], ah[mt][2], ah[mt][3], s0 + AOF + off);
            }
            // B fragments (4 n-tile pairs -> 8 n-tiles)
            #pragma unroll
            for (int np = 0; np < 4; np++) {
                int n = warp_n * 64 + np * 16 + b_nlane;
                uint32_t off = (uint32_t)(n * 64 + (((ks * 2 + b_kh) ^ (n & 3)) << 4));
                LDSM_X4(bh[np * 4 + 0], bh[np * 4 + 1], bh[np * 4 + 2], bh[np * 4 + 3],
                        s0 + BOF + off);
            }
            #pragma unroll
            for (int mt = 0; mt < 2; mt++) {
                #pragma unroll
                for (int nt = 0; nt < 8; nt++) {
                    int bi = (nt >> 1) * 4 + (nt & 1) * 2;
                    MMA_16816(acc[mt][nt], ah[mt][0], ah[mt][1], ah[mt][2], ah[mt][3],
                              bh[bi], bh[bi + 1]);
                }
            }
        }
    }

    // ---- epilogue: bias + leaky + Wc contraction, quad reduce, atomicAdd ----
    float part[2][2][4];
    #pragma unroll
    for (int mt = 0; mt < 2; mt++)
        #pragma unroll
        for (int h = 0; h < 2; h++)
            #pragma unroll
            for (int s = 0; s < 4; s++) part[mt][h][s] = 0.0f;

    #pragma unroll
    for (int nt = 0; nt < 8; nt++) {
        #pragma unroll
        for (int e = 0; e < 4; e++) {
            int n = n0 + warp_n * 64 + nt * 8 + (lane & 3) * 2 + (e & 1);
            if (n >= NTOT) continue;
            float bias = (n < MLPD) ? __ldg(bdep + n) : __ldg(bhead + n - MLPD);
            float w0 = __ldg(Wc + 2 * n);
            float w1 = __ldg(Wc + 2 * n + 1);
            int s = (n < MLPD) ? 0 : 2;
            int half = e >> 1;
            #pragma unroll
            for (int mt = 0; mt < 2; mt++) {
                float v = acc[mt][nt][e] + bias;
                v = (v > 0.0f) ? v : NEG_SLOPE * v;
                part[mt][half][s + 0] += v * w0;
                part[mt][half][s + 1] += v * w1;
            }
        }
    }

    // reduce across the 4 lanes of each quad (they share the same rows)
    #pragma unroll
    for (int mt = 0; mt < 2; mt++)
        #pragma unroll
        for (int h = 0; h < 2; h++)
            #pragma unroll
            for (int s = 0; s < 4; s++) {
                float v = part[mt][h][s];
                v += __shfl_xor_sync(0xffffffffu, v, 1);
                v += __shfl_xor_sync(0xffffffffu, v, 2);
                part[mt][h][s] = v;
            }

    if ((lane & 3) == 0) {
        #pragma unroll
        for (int mt = 0; mt < 2; mt++)
            #pragma unroll
            for (int h = 0; h < 2; h++) {
                int row = row0 + warp_m * 32 + mt * 16 + (lane >> 2) + h * 8;
                #pragma unroll
                for (int s = 0; s < 4; s++)
                    atomicAdd(&g_scores[row * 4 + s], part[mt][h][s]);
            }
    }
}

// ---------------------------------------------------------------------------
// Kernel 4: broadcast pairwise add -> out[b,i,j,c]
// ---------------------------------------------------------------------------
__global__ __launch_bounds__(256)
void broadcast_add_kernel(const float* __restrict__ bc, float* __restrict__ out) {
    __shared__ float hs[SEQ * 2];
    const int row = blockIdx.x;
    const int b   = row >> 10;
    const int tid = threadIdx.x;

    for (int j = tid; j < SEQ; j += 256) {
        int hr = (b << 10) + j;
        hs[2 * j + 0] = g_scores[hr * 4 + 2];
        hs[2 * j + 1] = g_scores[hr * 4 + 3];
    }
    __syncthreads();

    const float d0 = g_scores[row * 4 + 0] + bc[0];
    const float d1 = g_scores[row * 4 + 1] + bc[1];

    float4* o = reinterpret_cast<float4*>(out + (size_t)row * (SEQ * 2));
    for (int f = tid; f < SEQ * 2 / 4; f += 256) {
        int j = 2 * f;
        float4 v;
        v.x = d0 + hs[2 * j + 0];
        v.y = d1 + hs[2 * j + 1];
        v.z = d0 + hs[2 * j + 2];
        v.w = d1 + hs[2 * j + 3];
        o[f] = v;
    }
}

// ---------------------------------------------------------------------------
// Launch
// ---------------------------------------------------------------------------
extern "C" void kernel_launch(void* const* d_in, const int* in_sizes, int n_in,
                              void* d_out, int out_size)
{
    (void)in_sizes; (void)n_in; (void)out_size;
    const float* hidden = (const float*)d_in[0];
    const float* Wd     = (const float*)d_in[1];
    const float* bd     = (const float*)d_in[2];
    const float* Wh     = (const float*)d_in[3];
    const float* bh     = (const float*)d_in[4];
    const float* Wc     = (const float*)d_in[5];
    const float* bc     = (const float*)d_in[6];
    float* out          = (float*)d_out;

    cudaFuncSetAttribute(gemm_mma_kernel,
                         cudaFuncAttributeMaxDynamicSharedMemorySize, DYN_SMEM);

    zero_scores_kernel<<<(ROWS * 4 + 255) / 256, 256>>>();
    convert_a_kernel<<<ROWS * DDIM / 4 / 256, 256>>>(hidden);
    transpose_w_kernel<<<dim3(NPAD / 32, DDIM / 32), dim3(32, 8)>>>(Wd, Wh);
    gemm_mma_kernel<<<dim3(NPAD / BN, ROWS / BM), 256, DYN_SMEM>>>(bd, bh, Wc);
    broadcast_add_kernel<<<ROWS, 256>>>(bc, out);
}

// round 15
// speedup vs baseline: 1.5350x; 1.3331x over previous
#include <cuda_runtime.h>
#include <cuda_fp16.h>
#include <stdint.h>

// ---------------------------------------------------------------------------
// Problem dims (fixed by reference setup_inputs)
// ---------------------------------------------------------------------------
#define BATCH   16
#define SEQ     1024
#define DDIM    1024
#define MLPD    500
#define ROWS    (BATCH * SEQ)     // 16384
#define NTOT    (2 * MLPD)        // 1000
#define NPAD    1024
#define NEG_SLOPE 0.01f

// ---------------------------------------------------------------------------
// Device scratch. Plain fp16 A and B (validated: rel_err 2.74e-4 vs 1e-3).
// ---------------------------------------------------------------------------
__device__ float   g_scores[ROWS * 4];
__device__ __half  g_a[ROWS * DDIM];         // 32 MB
__device__ __half  g_wt[NPAD * DDIM];        // 2 MB  [n][k], rows >=1000 zero

// ---------------------------------------------------------------------------
// Helpers (sm_100-safe: cp.async / ldmatrix / mma.sync only)
// ---------------------------------------------------------------------------
__device__ __forceinline__ uint32_t smem_u32(const void* p) {
    uint32_t a;
    asm("{ .reg .u64 t; cvta.to.shared.u64 t, %1; cvt.u32.u64 %0, t; }"
        : "=r"(a) : "l"(p));
    return a;
}

#define CP_ASYNC16(dst, src) \
    asm volatile("cp.async.cg.shared.global [%0], [%1], 16;" \
                 :: "r"(dst), "l"(src) : "memory")
#define CP_COMMIT()  asm volatile("cp.async.commit_group;" ::: "memory")
#define CP_WAIT1()   asm volatile("cp.async.wait_group 1;" ::: "memory")

#define LDSM_X4(r0, r1, r2, r3, addr) \
    asm volatile("ldmatrix.sync.aligned.m8n8.x4.shared.b16 {%0,%1,%2,%3}, [%4];" \
                 : "=r"(r0), "=r"(r1), "=r"(r2), "=r"(r3) : "r"(addr))

#define MMA_16816(d, a0, a1, a2, a3, b0, b1) \
    asm volatile("mma.sync.aligned.m16n8k16.row.col.f32.f16.f16.f32 " \
                 "{%0,%1,%2,%3}, {%4,%5,%6,%7}, {%8,%9}, {%0,%1,%2,%3};" \
                 : "+f"((d)[0]), "+f"((d)[1]), "+f"((d)[2]), "+f"((d)[3]) \
                 : "r"(a0), "r"(a1), "r"(a2), "r"(a3), "r"(b0), "r"(b1))

// ---------------------------------------------------------------------------
// Kernel 0: zero scores scratch
// ---------------------------------------------------------------------------
__global__ void zero_scores_kernel() {
    int idx = blockIdx.x * blockDim.x + threadIdx.x;
    if (idx < ROWS * 4) g_scores[idx] = 0.0f;
}

// ---------------------------------------------------------------------------
// Kernel 1: convert hidden fp32 -> fp16
// ---------------------------------------------------------------------------
__global__ __launch_bounds__(256)
void convert_a_kernel(const float* __restrict__ A) {
    int i = blockIdx.x * blockDim.x + threadIdx.x;        // float4 index
    float4 v = reinterpret_cast<const float4*>(A)[i];
    __half2 p0; p0.x = __float2half(v.x); p0.y = __float2half(v.y);
    __half2 p1; p1.x = __float2half(v.z); p1.y = __float2half(v.w);
    __half2* H = reinterpret_cast<__half2*>(g_a);
    H[2 * i + 0] = p0;  H[2 * i + 1] = p1;
}

// ---------------------------------------------------------------------------
// Kernel 2: transpose W_dep|W_head fp32 -> fp16 [NPAD][DDIM]
// ---------------------------------------------------------------------------
__global__ __launch_bounds__(256)
void transpose_w_kernel(const float* __restrict__ Wd, const float* __restrict__ Wh) {
    __shared__ float tile[32][33];
    const int n0 = blockIdx.x * 32;
    const int k0 = blockIdx.y * 32;
    const int tx = threadIdx.x, ty = threadIdx.y;    // 32 x 8

    #pragma unroll
    for (int i = 0; i < 4; i++) {
        int k = k0 + ty + i * 8;
        int n = n0 + tx;
        float val = 0.0f;
        if (n < MLPD)       val = Wd[(size_t)k * MLPD + n];
        else if (n < NTOT)  val = Wh[(size_t)k * MLPD + (n - MLPD)];
        tile[ty + i * 8][tx] = val;              // tile[kk][nn]
    }
    __syncthreads();
    #pragma unroll
    for (int i = 0; i < 4; i++) {
        int n = n0 + ty + i * 8;
        int k = k0 + tx;
        g_wt[(size_t)n * DDIM + k] = __float2half(tile[tx][ty + i * 8]);
    }
}

// ---------------------------------------------------------------------------
// Kernel 3: fp16 mma.sync GEMM + fused epilogue
// Grid (8, 128), 256 threads (8 warps: 4 m x 2 n), 128x128x64 CTA tile.
// Warp tile 32x64. 3-stage cp.async pipeline (BK=64: half the sync events
// of BK=32, double prefetch distance, identical L1 traffic).
// Rows are 128B in SMEM; swizzle chunk ^= (row & 7) keeps STS + LDSM
// conflict-free.
// ---------------------------------------------------------------------------
#define BM 128
#define BN 128
#define BK 64
#define STAGES 3
#define MAT_BYTES  (BM * BK * 2)      // 16384
#define STAGE_B    (2 * MAT_BYTES)    // 32768
#define AOF 0
#define BOF MAT_BYTES
#define DYN_SMEM   (STAGES * STAGE_B) // 98304

__global__ __launch_bounds__(256)
void gemm_mma_kernel(const float* __restrict__ bdep, const float* __restrict__ bhead,
                     const float* __restrict__ Wc) {
    extern __shared__ char smem[];
    const uint32_t sb = smem_u32(smem);

    const int tid    = threadIdx.x;
    const int lane   = tid & 31;
    const int wid    = tid >> 5;
    const int warp_m = wid & 3;        // 0..3  (32-row group)
    const int warp_n = wid >> 2;       // 0..1  (64-col group)
    const int row0   = blockIdx.y * BM;
    const int n0     = blockIdx.x * BN;

    // per-lane ldmatrix geometry
    const int a_mlane = (lane & 15);          // row within 16-row A tile
    const int a_kh    = lane >> 4;            // k-half (0/1)
    const int b_nlane = (lane & 7) + ((lane >> 4) << 3);  // row within 16-row B pair
    const int b_kh    = (lane >> 3) & 1;

    float acc[2][8][4];
    #pragma unroll
    for (int i = 0; i < 2; i++)
        #pragma unroll
        for (int j = 0; j < 8; j++)
            #pragma unroll
            for (int e = 0; e < 4; e++) acc[i][j][e] = 0.0f;

    // ---- stage loader: rows are 8 x 16B chunks; 4 iters x (A,B) per thread
    auto load_stage = [&](int stage, int kt) {
        const uint32_t s0 = sb + stage * STAGE_B;
        #pragma unroll
        for (int i = 0; i < 4; i++) {
            int idx = tid + i * 256;          // 0..1023
            int m  = idx >> 3;                // row 0..127
            int kc = idx & 7;                 // 16B chunk 0..7
            uint32_t doff = (uint32_t)(m * 128 + ((kc ^ (m & 7)) << 4));
            size_t gsrc  = (size_t)(row0 + m) * DDIM + kt + kc * 8;
            size_t gsrcB = (size_t)(n0 + m) * DDIM + kt + kc * 8;
            CP_ASYNC16(s0 + AOF + doff, (const void*)(g_a + gsrc));
            CP_ASYNC16(s0 + BOF + doff, (const void*)(g_wt + gsrcB));
        }
    };

    // prologue: stages 0 and 1
    load_stage(0, 0);
    CP_COMMIT();
    load_stage(1, BK);
    CP_COMMIT();

    const int NKC = DDIM / BK;   // 16
    for (int kc = 0; kc < NKC; kc++) {
        CP_WAIT1();
        __syncthreads();

        // issue loads for kc+2 into the stage freed last iteration
        if (kc + 2 < NKC) load_stage((kc + 2) % STAGES, (kc + 2) * BK);
        CP_COMMIT();

        const uint32_t s0 = sb + (kc % STAGES) * STAGE_B;

        #pragma unroll
        for (int ks = 0; ks < 4; ks++) {
            uint32_t ah[2][4], bh[16];
            // A fragments (2 m-tiles)
            #pragma unroll
            for (int mt = 0; mt < 2; mt++) {
                int m = warp_m * 32 + mt * 16 + a_mlane;
                uint32_t off = (uint32_t)(m * 128 + (((ks * 2 + a_kh) ^ (m & 7)) << 4));
                LDSM_X4(ah[mt][0], ah[mt][1], ah[mt][2], ah[mt][3], s0 + AOF + off);
            }
            // B fragments (4 n-tile pairs -> 8 n-tiles)
            #pragma unroll
            for (int np = 0; np < 4; np++) {
                int n = warp_n * 64 + np * 16 + b_nlane;
                uint32_t off = (uint32_t)(n * 128 + (((ks * 2 + b_kh) ^ (n & 7)) << 4));
                LDSM_X4(bh[np * 4 + 0], bh[np * 4 + 1], bh[np * 4 + 2], bh[np * 4 + 3],
                        s0 + BOF + off);
            }
            #pragma unroll
            for (int mt = 0; mt < 2; mt++) {
                #pragma unroll
                for (int nt = 0; nt < 8; nt++) {
                    int bi = (nt >> 1) * 4 + (nt & 1) * 2;
                    MMA_16816(acc[mt][nt], ah[mt][0], ah[mt][1], ah[mt][2], ah[mt][3],
                              bh[bi], bh[bi + 1]);
                }
            }
        }
    }

    // ---- epilogue: bias + leaky + Wc contraction, quad reduce, atomicAdd ----
    float part[2][2][4];
    #pragma unroll
    for (int mt = 0; mt < 2; mt++)
        #pragma unroll
        for (int h = 0; h < 2; h++)
            #pragma unroll
            for (int s = 0; s < 4; s++) part[mt][h][s] = 0.0f;

    #pragma unroll
    for (int nt = 0; nt < 8; nt++) {
        #pragma unroll
        for (int e = 0; e < 4; e++) {
            int n = n0 + warp_n * 64 + nt * 8 + (lane & 3) * 2 + (e & 1);
            if (n >= NTOT) continue;
            float bias = (n < MLPD) ? __ldg(bdep + n) : __ldg(bhead + n - MLPD);
            float w0 = __ldg(Wc + 2 * n);
            float w1 = __ldg(Wc + 2 * n + 1);
            int s = (n < MLPD) ? 0 : 2;
            int half = e >> 1;
            #pragma unroll
            for (int mt = 0; mt < 2; mt++) {
                float v = acc[mt][nt][e] + bias;
                v = (v > 0.0f) ? v : NEG_SLOPE * v;
                part[mt][half][s + 0] += v * w0;
                part[mt][half][s + 1] += v * w1;
            }
        }
    }

    // reduce across the 4 lanes of each quad (they share the same rows)
    #pragma unroll
    for (int mt = 0; mt < 2; mt++)
        #pragma unroll
        for (int h = 0; h < 2; h++)
            #pragma unroll
            for (int s = 0; s < 4; s++) {
                float v = part[mt][h][s];
                v += __shfl_xor_sync(0xffffffffu, v, 1);
                v += __shfl_xor_sync(0xffffffffu, v, 2);
                part[mt][h][s] = v;
            }

    if ((lane & 3) == 0) {
        #pragma unroll
        for (int mt = 0; mt < 2; mt++)
            #pragma unroll
            for (int h = 0; h < 2; h++) {
                int row = row0 + warp_m * 32 + mt * 16 + (lane >> 2) + h * 8;
                #pragma unroll
                for (int s = 0; s < 4; s++)
                    atomicAdd(&g_scores[row * 4 + s], part[mt][h][s]);
            }
    }
}

// ---------------------------------------------------------------------------
// Kernel 4: broadcast pairwise add -> out[b,i,j,c]
// ---------------------------------------------------------------------------
__global__ __launch_bounds__(256)
void broadcast_add_kernel(const float* __restrict__ bc, float* __restrict__ out) {
    __shared__ float hs[SEQ * 2];
    const int row = blockIdx.x;
    const int b   = row >> 10;
    const int tid = threadIdx.x;

    for (int j = tid; j < SEQ; j += 256) {
        int hr = (b << 10) + j;
        hs[2 * j + 0] = g_scores[hr * 4 + 2];
        hs[2 * j + 1] = g_scores[hr * 4 + 3];
    }
    __syncthreads();

    const float d0 = g_scores[row * 4 + 0] + bc[0];
    const float d1 = g_scores[row * 4 + 1] + bc[1];

    float4* o = reinterpret_cast<float4*>(out + (size_t)row * (SEQ * 2));
    for (int f = tid; f < SEQ * 2 / 4; f += 256) {
        int j = 2 * f;
        float4 v;
        v.x = d0 + hs[2 * j + 0];
        v.y = d1 + hs[2 * j + 1];
        v.z = d0 + hs[2 * j + 2];
        v.w = d1 + hs[2 * j + 3];
        o[f] = v;
    }
}

// ---------------------------------------------------------------------------
// Launch
// ---------------------------------------------------------------------------
extern "C" void kernel_launch(void* const* d_in, const int* in_sizes, int n_in,
                              void* d_out, int out_size)
{
    (void)in_sizes; (void)n_in; (void)out_size;
    const float* hidden = (const float*)d_in[0];
    const float* Wd     = (const float*)d_in[1];
    const float* bd     = (const float*)d_in[2];
    const float* Wh     = (const float*)d_in[3];
    const float* bh     = (const float*)d_in[4];
    const float* Wc     = (const float*)d_in[5];
    const float* bc     = (const float*)d_in[6];
    float* out          = (float*)d_out;

    cudaFuncSetAttribute(gemm_mma_kernel,
                         cudaFuncAttributeMaxDynamicSharedMemorySize, DYN_SMEM);

    zero_scores_kernel<<<(ROWS * 4 + 255) / 256, 256>>>();
    convert_a_kernel<<<ROWS * DDIM / 4 / 256, 256>>>(hidden);
    transpose_w_kernel<<<dim3(NPAD / 32, DDIM / 32), dim3(32, 8)>>>(Wd, Wh);
    gemm_mma_kernel<<<dim3(NPAD / BN, ROWS / BM), 256, DYN_SMEM>>>(bd, bh, Wc);
    broadcast_add_kernel<<<ROWS, 256>>>(bc, out);
}

// round 16
// speedup vs baseline: 1.7271x; 1.1251x over previous
#include <cuda_runtime.h>
#include <cuda_fp16.h>
#include <stdint.h>

// ---------------------------------------------------------------------------
// Problem dims (fixed by reference setup_inputs)
// ---------------------------------------------------------------------------
#define BATCH   16
#define SEQ     1024
#define DDIM    1024
#define MLPD    500
#define ROWS    (BATCH * SEQ)     // 16384
#define NTOT    (2 * MLPD)        // 1000
#define NPAD    1024
#define NEG_SLOPE 0.01f

// ---------------------------------------------------------------------------
// Device scratch. Plain fp16 A and B (validated: rel_err 2.74e-4 vs 1e-3).
// ---------------------------------------------------------------------------
__device__ float   g_scores[ROWS * 4];
__device__ __half  g_a[ROWS * DDIM];         // 32 MB
__device__ __half  g_wt[NPAD * DDIM];        // 2 MB  [n][k], rows >=1000 zero

// ---------------------------------------------------------------------------
// Helpers (sm_100-safe: cp.async / ldmatrix / mma.sync only)
// ---------------------------------------------------------------------------
__device__ __forceinline__ uint32_t smem_u32(const void* p) {
    uint32_t a;
    asm("{ .reg .u64 t; cvta.to.shared.u64 t, %1; cvt.u32.u64 %0, t; }"
        : "=r"(a) : "l"(p));
    return a;
}

#define CP_ASYNC16(dst, src) \
    asm volatile("cp.async.cg.shared.global [%0], [%1], 16;" \
                 :: "r"(dst), "l"(src) : "memory")
#define CP_COMMIT()  asm volatile("cp.async.commit_group;" ::: "memory")
#define CP_WAIT1()   asm volatile("cp.async.wait_group 1;" ::: "memory")

#define LDSM_X4(r0, r1, r2, r3, addr) \
    asm volatile("ldmatrix.sync.aligned.m8n8.x4.shared.b16 {%0,%1,%2,%3}, [%4];" \
                 : "=r"(r0), "=r"(r1), "=r"(r2), "=r"(r3) : "r"(addr))

#define MMA_16816(d, a0, a1, a2, a3, b0, b1) \
    asm volatile("mma.sync.aligned.m16n8k16.row.col.f32.f16.f16.f32 " \
                 "{%0,%1,%2,%3}, {%4,%5,%6,%7}, {%8,%9}, {%0,%1,%2,%3};" \
                 : "+f"((d)[0]), "+f"((d)[1]), "+f"((d)[2]), "+f"((d)[3]) \
                 : "r"(a0), "r"(a1), "r"(a2), "r"(a3), "r"(b0), "r"(b1))

// ---------------------------------------------------------------------------
// Kernel 1: convert hidden fp32 -> fp16 (also zero-fills g_scores)
// ---------------------------------------------------------------------------
__global__ __launch_bounds__(256)
void convert_a_kernel(const float* __restrict__ A) {
    int i = blockIdx.x * blockDim.x + threadIdx.x;        // float4 index
    if (i < ROWS * 4) g_scores[i] = 0.0f;                 // fused zero (64K < 4.2M threads)
    float4 v = reinterpret_cast<const float4*>(A)[i];
    __half2 p0; p0.x = __float2half(v.x); p0.y = __float2half(v.y);
    __half2 p1; p1.x = __float2half(v.z); p1.y = __float2half(v.w);
    __half2* H = reinterpret_cast<__half2*>(g_a);
    H[2 * i + 0] = p0;  H[2 * i + 1] = p1;
}

// ---------------------------------------------------------------------------
// Kernel 2: transpose W_dep|W_head fp32 -> fp16 [NPAD][DDIM]
// ---------------------------------------------------------------------------
__global__ __launch_bounds__(256)
void transpose_w_kernel(const float* __restrict__ Wd, const float* __restrict__ Wh) {
    __shared__ float tile[32][33];
    const int n0 = blockIdx.x * 32;
    const int k0 = blockIdx.y * 32;
    const int tx = threadIdx.x, ty = threadIdx.y;    // 32 x 8

    #pragma unroll
    for (int i = 0; i < 4; i++) {
        int k = k0 + ty + i * 8;
        int n = n0 + tx;
        float val = 0.0f;
        if (n < MLPD)       val = Wd[(size_t)k * MLPD + n];
        else if (n < NTOT)  val = Wh[(size_t)k * MLPD + (n - MLPD)];
        tile[ty + i * 8][tx] = val;              // tile[kk][nn]
    }
    __syncthreads();
    #pragma unroll
    for (int i = 0; i < 4; i++) {
        int n = n0 + ty + i * 8;
        int k = k0 + tx;
        g_wt[(size_t)n * DDIM + k] = __float2half(tile[tx][ty + i * 8]);
    }
}

// ---------------------------------------------------------------------------
// Kernel 3: fp16 mma.sync GEMM + fused epilogue
// Grid (8, 128), 256 threads (8 warps: 4 m x 2 n), 128x128x64 CTA tile.
// Warp tile 32x64. 3-stage cp.async pipeline, BK=64.
// Issue order: ks=0 fragment LDSMs BEFORE the prefetch cp.async batch
// (they share the MIO queue; critical loads go first).
// ---------------------------------------------------------------------------
#define BM 128
#define BN 128
#define BK 64
#define STAGES 3
#define MAT_BYTES  (BM * BK * 2)      // 16384
#define STAGE_B    (2 * MAT_BYTES)    // 32768
#define AOF 0
#define BOF MAT_BYTES
#define DYN_SMEM   (STAGES * STAGE_B) // 98304

__global__ __launch_bounds__(256, 2)
void gemm_mma_kernel(const float* __restrict__ bdep, const float* __restrict__ bhead,
                     const float* __restrict__ Wc) {
    extern __shared__ char smem[];
    const uint32_t sb = smem_u32(smem);

    const int tid    = threadIdx.x;
    const int lane   = tid & 31;
    const int wid    = tid >> 5;
    const int warp_m = wid & 3;        // 0..3  (32-row group)
    const int warp_n = wid >> 2;       // 0..1  (64-col group)
    const int row0   = blockIdx.y * BM;
    const int n0     = blockIdx.x * BN;

    // per-lane ldmatrix geometry
    const int a_mlane = (lane & 15);          // row within 16-row A tile
    const int a_kh    = lane >> 4;            // k-half (0/1)
    const int b_nlane = (lane & 7) + ((lane >> 4) << 3);  // row within 16-row B pair
    const int b_kh    = (lane >> 3) & 1;

    float acc[2][8][4];
    #pragma unroll
    for (int i = 0; i < 2; i++)
        #pragma unroll
        for (int j = 0; j < 8; j++)
            #pragma unroll
            for (int e = 0; e < 4; e++) acc[i][j][e] = 0.0f;

    // ---- stage loader: rows are 8 x 16B chunks; 4 iters x (A,B) per thread
    auto load_stage = [&](int stage, int kt) {
        const uint32_t s0 = sb + stage * STAGE_B;
        #pragma unroll
        for (int i = 0; i < 4; i++) {
            int idx = tid + i * 256;          // 0..1023
            int m  = idx >> 3;                // row 0..127
            int kc = idx & 7;                 // 16B chunk 0..7
            uint32_t doff = (uint32_t)(m * 128 + ((kc ^ (m & 7)) << 4));
            size_t gsrc  = (size_t)(row0 + m) * DDIM + kt + kc * 8;
            size_t gsrcB = (size_t)(n0 + m) * DDIM + kt + kc * 8;
            CP_ASYNC16(s0 + AOF + doff, (const void*)(g_a + gsrc));
            CP_ASYNC16(s0 + BOF + doff, (const void*)(g_wt + gsrcB));
        }
    };

    // fragment loader for one k-step from stage base s0
    auto load_frags = [&](uint32_t s0, int ks, uint32_t ah[2][4], uint32_t bh[16]) {
        #pragma unroll
        for (int mt = 0; mt < 2; mt++) {
            int m = warp_m * 32 + mt * 16 + a_mlane;
            uint32_t off = (uint32_t)(m * 128 + (((ks * 2 + a_kh) ^ (m & 7)) << 4));
            LDSM_X4(ah[mt][0], ah[mt][1], ah[mt][2], ah[mt][3], s0 + AOF + off);
        }
        #pragma unroll
        for (int np = 0; np < 4; np++) {
            int n = warp_n * 64 + np * 16 + b_nlane;
            uint32_t off = (uint32_t)(n * 128 + (((ks * 2 + b_kh) ^ (n & 7)) << 4));
            LDSM_X4(bh[np * 4 + 0], bh[np * 4 + 1], bh[np * 4 + 2], bh[np * 4 + 3],
                    s0 + BOF + off);
        }
    };
    auto do_mmas = [&](uint32_t ah[2][4], uint32_t bh[16]) {
        #pragma unroll
        for (int mt = 0; mt < 2; mt++) {
            #pragma unroll
            for (int nt = 0; nt < 8; nt++) {
                int bi = (nt >> 1) * 4 + (nt & 1) * 2;
                MMA_16816(acc[mt][nt], ah[mt][0], ah[mt][1], ah[mt][2], ah[mt][3],
                          bh[bi], bh[bi + 1]);
            }
        }
    };

    // prologue: stages 0 and 1
    load_stage(0, 0);
    CP_COMMIT();
    load_stage(1, BK);
    CP_COMMIT();

    const int NKC = DDIM / BK;   // 16
    int st  = 0;                 // stage of current kc
    int stp = 2;                 // stage of kc+2
    for (int kc = 0; kc < NKC; kc++) {
        CP_WAIT1();
        __syncthreads();

        const uint32_t s0 = sb + st * STAGE_B;

        // critical fragments for ks=0 FIRST, then the prefetch batch
        uint32_t ah[2][4], bh[16];
        load_frags(s0, 0, ah, bh);

        if (kc + 2 < NKC) load_stage(stp, (kc + 2) * BK);
        CP_COMMIT();

        do_mmas(ah, bh);

        #pragma unroll
        for (int ks = 1; ks < 4; ks++) {
            uint32_t ah2[2][4], bh2[16];
            load_frags(s0, ks, ah2, bh2);
            do_mmas(ah2, bh2);
        }

        st  = (st  == 2) ? 0 : st  + 1;
        stp = (stp == 2) ? 0 : stp + 1;
    }

    // ---- epilogue: bias + leaky + Wc contraction, quad reduce, atomicAdd ----
    float part[2][2][4];
    #pragma unroll
    for (int mt = 0; mt < 2; mt++)
        #pragma unroll
        for (int h = 0; h < 2; h++)
            #pragma unroll
            for (int s = 0; s < 4; s++) part[mt][h][s] = 0.0f;

    #pragma unroll
    for (int nt = 0; nt < 8; nt++) {
        #pragma unroll
        for (int e = 0; e < 4; e++) {
            int n = n0 + warp_n * 64 + nt * 8 + (lane & 3) * 2 + (e & 1);
            if (n >= NTOT) continue;
            float bias = (n < MLPD) ? __ldg(bdep + n) : __ldg(bhead + n - MLPD);
            float w0 = __ldg(Wc + 2 * n);
            float w1 = __ldg(Wc + 2 * n + 1);
            int s = (n < MLPD) ? 0 : 2;
            int half = e >> 1;
            #pragma unroll
            for (int mt = 0; mt < 2; mt++) {
                float v = acc[mt][nt][e] + bias;
                v = (v > 0.0f) ? v : NEG_SLOPE * v;
                part[mt][half][s + 0] += v * w0;
                part[mt][half][s + 1] += v * w1;
            }
        }
    }

    // reduce across the 4 lanes of each quad (they share the same rows)
    #pragma unroll
    for (int mt = 0; mt < 2; mt++)
        #pragma unroll
        for (int h = 0; h < 2; h++)
            #pragma unroll
            for (int s = 0; s < 4; s++) {
                float v = part[mt][h][s];
                v += __shfl_xor_sync(0xffffffffu, v, 1);
                v += __shfl_xor_sync(0xffffffffu, v, 2);
                part[mt][h][s] = v;
            }

    if ((lane & 3) == 0) {
        #pragma unroll
        for (int mt = 0; mt < 2; mt++)
            #pragma unroll
            for (int h = 0; h < 2; h++) {
                int row = row0 + warp_m * 32 + mt * 16 + (lane >> 2) + h * 8;
                #pragma unroll
                for (int s = 0; s < 4; s++)
                    atomicAdd(&g_scores[row * 4 + s], part[mt][h][s]);
            }
    }
}

// ---------------------------------------------------------------------------
// Kernel 4: broadcast pairwise add -> out[b,i,j,c]  (4 rows per block)
// ---------------------------------------------------------------------------
#define BCAST_ROWS 4
__global__ __launch_bounds__(256)
void broadcast_add_kernel(const float* __restrict__ bc, float* __restrict__ out) {
    __shared__ float hs[SEQ * 2];
    const int r0  = blockIdx.x * BCAST_ROWS;   // 4 rows, same batch (SEQ%4==0)
    const int b   = r0 >> 10;
    const int tid = threadIdx.x;

    for (int j = tid; j < SEQ; j += 256) {
        int hr = (b << 10) + j;
        hs[2 * j + 0] = g_scores[hr * 4 + 2];
        hs[2 * j + 1] = g_scores[hr * 4 + 3];
    }
    __syncthreads();

    #pragma unroll
    for (int rr = 0; rr < BCAST_ROWS; rr++) {
        const int row = r0 + rr;
        const float d0 = g_scores[row * 4 + 0] + bc[0];
        const float d1 = g_scores[row * 4 + 1] + bc[1];
        float4* o = reinterpret_cast<float4*>(out + (size_t)row * (SEQ * 2));
        for (int f = tid; f < SEQ * 2 / 4; f += 256) {
            int j = 2 * f;
            float4 v;
            v.x = d0 + hs[2 * j + 0];
            v.y = d1 + hs[2 * j + 1];
            v.z = d0 + hs[2 * j + 2];
            v.w = d1 + hs[2 * j + 3];
            o[f] = v;
        }
    }
}

// ---------------------------------------------------------------------------
// Launch
// ---------------------------------------------------------------------------
extern "C" void kernel_launch(void* const* d_in, const int* in_sizes, int n_in,
                              void* d_out, int out_size)
{
    (void)in_sizes; (void)n_in; (void)out_size;
    const float* hidden = (const float*)d_in[0];
    const float* Wd     = (const float*)d_in[1];
    const float* bd     = (const float*)d_in[2];
    const float* Wh     = (const float*)d_in[3];
    const float* bh     = (const float*)d_in[4];
    const float* Wc     = (const float*)d_in[5];
    const float* bc     = (const float*)d_in[6];
    float* out          = (float*)d_out;

    cudaFuncSetAttribute(gemm_mma_kernel,
                         cudaFuncAttributeMaxDynamicSharedMemorySize, DYN_SMEM);

    convert_a_kernel<<<ROWS * DDIM / 4 / 256, 256>>>(hidden);
    transpose_w_kernel<<<dim3(NPAD / 32, DDIM / 32), dim3(32, 8)>>>(Wd, Wh);
    gemm_mma_kernel<<<dim3(NPAD / BN, ROWS / BM), 256, DYN_SMEM>>>(bd, bh, Wc);
    broadcast_add_kernel<<<ROWS / BCAST_ROWS, 256>>>(bc, out);
}

// round 17
// speedup vs baseline: 1.7577x; 1.0177x over previous
#include <cuda_runtime.h>
#include <cuda_fp16.h>
#include <stdint.h>

// ---------------------------------------------------------------------------
// Problem dims (fixed by reference setup_inputs)
// ---------------------------------------------------------------------------
#define BATCH   16
#define SEQ     1024
#define DDIM    1024
#define MLPD    500
#define ROWS    (BATCH * SEQ)     // 16384
#define NTOT    (2 * MLPD)        // 1000
#define NPAD    1024
#define NEG_SLOPE 0.01f

// ---------------------------------------------------------------------------
// Device scratch. Plain fp16 A and B (validated: rel_err 2.74e-4 vs 1e-3).
// ---------------------------------------------------------------------------
__device__ float   g_scores[ROWS * 4];
__device__ __half  g_a[ROWS * DDIM];         // 32 MB
__device__ __half  g_wt[NPAD * DDIM];        // 2 MB  [n][k], rows >=1000 zero

// ---------------------------------------------------------------------------
// Helpers (sm_100-safe: cp.async / ldmatrix / mma.sync only)
// ---------------------------------------------------------------------------
__device__ __forceinline__ uint32_t smem_u32(const void* p) {
    uint32_t a;
    asm("{ .reg .u64 t; cvta.to.shared.u64 t, %1; cvt.u32.u64 %0, t; }"
        : "=r"(a) : "l"(p));
    return a;
}

#define CP_ASYNC16(dst, src) \
    asm volatile("cp.async.cg.shared.global [%0], [%1], 16;" \
                 :: "r"(dst), "l"(src) : "memory")
#define CP_COMMIT()  asm volatile("cp.async.commit_group;" ::: "memory")
#define CP_WAIT1()   asm volatile("cp.async.wait_group 1;" ::: "memory")

#define LDSM_X4(r0, r1, r2, r3, addr) \
    asm volatile("ldmatrix.sync.aligned.m8n8.x4.shared.b16 {%0,%1,%2,%3}, [%4];" \
                 : "=r"(r0), "=r"(r1), "=r"(r2), "=r"(r3) : "r"(addr))

#define MMA_16816(d, a0, a1, a2, a3, b0, b1) \
    asm volatile("mma.sync.aligned.m16n8k16.row.col.f32.f16.f16.f32 " \
                 "{%0,%1,%2,%3}, {%4,%5,%6,%7}, {%8,%9}, {%0,%1,%2,%3};" \
                 : "+f"((d)[0]), "+f"((d)[1]), "+f"((d)[2]), "+f"((d)[3]) \
                 : "r"(a0), "r"(a1), "r"(a2), "r"(a3), "r"(b0), "r"(b1))

// ---------------------------------------------------------------------------
// Kernel 1: convert hidden fp32 -> fp16 (also zero-fills g_scores)
// ---------------------------------------------------------------------------
__global__ __launch_bounds__(256)
void convert_a_kernel(const float* __restrict__ A) {
    int i = blockIdx.x * blockDim.x + threadIdx.x;        // float4 index
    if (i < ROWS * 4) g_scores[i] = 0.0f;                 // fused zero (64K < 4.2M threads)
    float4 v = reinterpret_cast<const float4*>(A)[i];
    __half2 p0; p0.x = __float2half(v.x); p0.y = __float2half(v.y);
    __half2 p1; p1.x = __float2half(v.z); p1.y = __float2half(v.w);
    __half2* H = reinterpret_cast<__half2*>(g_a);
    H[2 * i + 0] = p0;  H[2 * i + 1] = p1;
}

// ---------------------------------------------------------------------------
// Kernel 2: transpose W_dep|W_head fp32 -> fp16 [NPAD][DDIM]
// ---------------------------------------------------------------------------
__global__ __launch_bounds__(256)
void transpose_w_kernel(const float* __restrict__ Wd, const float* __restrict__ Wh) {
    __shared__ float tile[32][33];
    const int n0 = blockIdx.x * 32;
    const int k0 = blockIdx.y * 32;
    const int tx = threadIdx.x, ty = threadIdx.y;    // 32 x 8

    #pragma unroll
    for (int i = 0; i < 4; i++) {
        int k = k0 + ty + i * 8;
        int n = n0 + tx;
        float val = 0.0f;
        if (n < MLPD)       val = Wd[(size_t)k * MLPD + n];
        else if (n < NTOT)  val = Wh[(size_t)k * MLPD + (n - MLPD)];
        tile[ty + i * 8][tx] = val;              // tile[kk][nn]
    }
    __syncthreads();
    #pragma unroll
    for (int i = 0; i < 4; i++) {
        int n = n0 + ty + i * 8;
        int k = k0 + tx;
        g_wt[(size_t)n * DDIM + k] = __float2half(tile[tx][ty + i * 8]);
    }
}

// ---------------------------------------------------------------------------
// Kernel 3: fp16 mma.sync GEMM + fused epilogue
// Grid (8, 128), 256 threads (8 warps: 4 m x 2 n), 128x128x64 CTA tile.
// Warp tile 32x64. 3-stage cp.async pipeline, BK=64.
// Issue order: ks=0 fragment LDSMs BEFORE the prefetch cp.async batch.
// ---------------------------------------------------------------------------
#define BM 128
#define BN 128
#define BK 64
#define STAGES 3
#define MAT_BYTES  (BM * BK * 2)      // 16384
#define STAGE_B    (2 * MAT_BYTES)    // 32768
#define AOF 0
#define BOF MAT_BYTES
#define DYN_SMEM   (STAGES * STAGE_B) // 98304

__global__ __launch_bounds__(256, 2)
void gemm_mma_kernel(const float* __restrict__ bdep, const float* __restrict__ bhead,
                     const float* __restrict__ Wc) {
    extern __shared__ char smem[];
    const uint32_t sb = smem_u32(smem);

    const int tid    = threadIdx.x;
    const int lane   = tid & 31;
    const int wid    = tid >> 5;
    const int warp_m = wid & 3;        // 0..3  (32-row group)
    const int warp_n = wid >> 2;       // 0..1  (64-col group)
    const int row0   = blockIdx.y * BM;
    const int n0     = blockIdx.x * BN;

    // per-lane ldmatrix geometry
    const int a_mlane = (lane & 15);          // row within 16-row A tile
    const int a_kh    = lane >> 4;            // k-half (0/1)
    const int b_nlane = (lane & 7) + ((lane >> 4) << 3);  // row within 16-row B pair
    const int b_kh    = (lane >> 3) & 1;

    float acc[2][8][4];
    #pragma unroll
    for (int i = 0; i < 2; i++)
        #pragma unroll
        for (int j = 0; j < 8; j++)
            #pragma unroll
            for (int e = 0; e < 4; e++) acc[i][j][e] = 0.0f;

    // ---- stage loader: rows are 8 x 16B chunks; 4 iters x (A,B) per thread
    auto load_stage = [&](int stage, int kt) {
        const uint32_t s0 = sb + stage * STAGE_B;
        #pragma unroll
        for (int i = 0; i < 4; i++) {
            int idx = tid + i * 256;          // 0..1023
            int m  = idx >> 3;                // row 0..127
            int kc = idx & 7;                 // 16B chunk 0..7
            uint32_t doff = (uint32_t)(m * 128 + ((kc ^ (m & 7)) << 4));
            size_t gsrc  = (size_t)(row0 + m) * DDIM + kt + kc * 8;
            size_t gsrcB = (size_t)(n0 + m) * DDIM + kt + kc * 8;
            CP_ASYNC16(s0 + AOF + doff, (const void*)(g_a + gsrc));
            CP_ASYNC16(s0 + BOF + doff, (const void*)(g_wt + gsrcB));
        }
    };

    // fragment loader for one k-step from stage base s0
    auto load_frags = [&](uint32_t s0, int ks, uint32_t ah[2][4], uint32_t bh[16]) {
        #pragma unroll
        for (int mt = 0; mt < 2; mt++) {
            int m = warp_m * 32 + mt * 16 + a_mlane;
            uint32_t off = (uint32_t)(m * 128 + (((ks * 2 + a_kh) ^ (m & 7)) << 4));
            LDSM_X4(ah[mt][0], ah[mt][1], ah[mt][2], ah[mt][3], s0 + AOF + off);
        }
        #pragma unroll
        for (int np = 0; np < 4; np++) {
            int n = warp_n * 64 + np * 16 + b_nlane;
            uint32_t off = (uint32_t)(n * 128 + (((ks * 2 + b_kh) ^ (n & 7)) << 4));
            LDSM_X4(bh[np * 4 + 0], bh[np * 4 + 1], bh[np * 4 + 2], bh[np * 4 + 3],
                    s0 + BOF + off);
        }
    };
    auto do_mmas = [&](uint32_t ah[2][4], uint32_t bh[16]) {
        #pragma unroll
        for (int mt = 0; mt < 2; mt++) {
            #pragma unroll
            for (int nt = 0; nt < 8; nt++) {
                int bi = (nt >> 1) * 4 + (nt & 1) * 2;
                MMA_16816(acc[mt][nt], ah[mt][0], ah[mt][1], ah[mt][2], ah[mt][3],
                          bh[bi], bh[bi + 1]);
            }
        }
    };

    // prologue: stages 0 and 1
    load_stage(0, 0);
    CP_COMMIT();
    load_stage(1, BK);
    CP_COMMIT();

    const int NKC = DDIM / BK;   // 16
    int st  = 0;                 // stage of current kc
    int stp = 2;                 // stage of kc+2
    for (int kc = 0; kc < NKC; kc++) {
        CP_WAIT1();
        __syncthreads();

        const uint32_t s0 = sb + st * STAGE_B;

        // critical fragments for ks=0 FIRST, then the prefetch batch
        uint32_t ah[2][4], bh[16];
        load_frags(s0, 0, ah, bh);

        if (kc + 2 < NKC) load_stage(stp, (kc + 2) * BK);
        CP_COMMIT();

        do_mmas(ah, bh);

        #pragma unroll
        for (int ks = 1; ks < 4; ks++) {
            uint32_t ah2[2][4], bh2[16];
            load_frags(s0, ks, ah2, bh2);
            do_mmas(ah2, bh2);
        }

        st  = (st  == 2) ? 0 : st  + 1;
        stp = (stp == 2) ? 0 : stp + 1;
    }

    // ---- epilogue: bias + leaky + Wc contraction, quad reduce, atomicAdd ----
    float part[2][2][4];
    #pragma unroll
    for (int mt = 0; mt < 2; mt++)
        #pragma unroll
        for (int h = 0; h < 2; h++)
            #pragma unroll
            for (int s = 0; s < 4; s++) part[mt][h][s] = 0.0f;

    #pragma unroll
    for (int nt = 0; nt < 8; nt++) {
        #pragma unroll
        for (int e = 0; e < 4; e++) {
            int n = n0 + warp_n * 64 + nt * 8 + (lane & 3) * 2 + (e & 1);
            if (n >= NTOT) continue;
            float bias = (n < MLPD) ? __ldg(bdep + n) : __ldg(bhead + n - MLPD);
            float w0 = __ldg(Wc + 2 * n);
            float w1 = __ldg(Wc + 2 * n + 1);
            int s = (n < MLPD) ? 0 : 2;
            int half = e >> 1;
            #pragma unroll
            for (int mt = 0; mt < 2; mt++) {
                float v = acc[mt][nt][e] + bias;
                v = (v > 0.0f) ? v : NEG_SLOPE * v;
                part[mt][half][s + 0] += v * w0;
                part[mt][half][s + 1] += v * w1;
            }
        }
    }

    // reduce across the 4 lanes of each quad (they share the same rows)
    #pragma unroll
    for (int mt = 0; mt < 2; mt++)
        #pragma unroll
        for (int h = 0; h < 2; h++)
            #pragma unroll
            for (int s = 0; s < 4; s++) {
                float v = part[mt][h][s];
                v += __shfl_xor_sync(0xffffffffu, v, 1);
                v += __shfl_xor_sync(0xffffffffu, v, 2);
                part[mt][h][s] = v;
            }

    if ((lane & 3) == 0) {
        #pragma unroll
        for (int mt = 0; mt < 2; mt++)
            #pragma unroll
            for (int h = 0; h < 2; h++) {
                int row = row0 + warp_m * 32 + mt * 16 + (lane >> 2) + h * 8;
                #pragma unroll
                for (int s = 0; s < 4; s++)
                    atomicAdd(&g_scores[row * 4 + s], part[mt][h][s]);
            }
    }
}

// ---------------------------------------------------------------------------
// Kernel 4: broadcast pairwise add -> out[b,i,j,c]
// 8 rows per block; hs read as float4 (LDS.128); streaming stores (__stcs).
// ---------------------------------------------------------------------------
#define BCAST_ROWS 8
__global__ __launch_bounds__(256)
void broadcast_add_kernel(const float* __restrict__ bc, float* __restrict__ out) {
    __shared__ __align__(16) float hs[SEQ * 2];
    const int r0  = blockIdx.x * BCAST_ROWS;   // 8 rows, same batch (SEQ%8==0)
    const int b   = r0 >> 10;
    const int tid = threadIdx.x;

    for (int j = tid; j < SEQ; j += 256) {
        int hr = (b << 10) + j;
        hs[2 * j + 0] = g_scores[hr * 4 + 2];
        hs[2 * j + 1] = g_scores[hr * 4 + 3];
    }
    __syncthreads();

    const float4* hs4 = reinterpret_cast<const float4*>(hs);   // 512 float4

    #pragma unroll
    for (int rr = 0; rr < BCAST_ROWS; rr++) {
        const int row = r0 + rr;
        const float d0 = g_scores[row * 4 + 0] + bc[0];
        const float d1 = g_scores[row * 4 + 1] + bc[1];
        float4* o = reinterpret_cast<float4*>(out + (size_t)row * (SEQ * 2));
        #pragma unroll 2
        for (int f = tid; f < SEQ * 2 / 4; f += 256) {   // 512 float4 per row
            float4 h = hs4[f];                            // one LDS.128
            float4 v;
            v.x = d0 + h.x;
            v.y = d1 + h.y;
            v.z = d0 + h.z;
            v.w = d1 + h.w;
            __stcs(&o[f], v);                             // streaming store
        }
    }
}

// ---------------------------------------------------------------------------
// Launch
// ---------------------------------------------------------------------------
extern "C" void kernel_launch(void* const* d_in, const int* in_sizes, int n_in,
                              void* d_out, int out_size)
{
    (void)in_sizes; (void)n_in; (void)out_size;
    const float* hidden = (const float*)d_in[0];
    const float* Wd     = (const float*)d_in[1];
    const float* bd     = (const float*)d_in[2];
    const float* Wh     = (const float*)d_in[3];
    const float* bh     = (const float*)d_in[4];
    const float* Wc     = (const float*)d_in[5];
    const float* bc     = (const float*)d_in[6];
    float* out          = (float*)d_out;

    cudaFuncSetAttribute(gemm_mma_kernel,
                         cudaFuncAttributeMaxDynamicSharedMemorySize, DYN_SMEM);

    convert_a_kernel<<<ROWS * DDIM / 4 / 256, 256>>>(hidden);
    transpose_w_kernel<<<dim3(NPAD / 32, DDIM / 32), dim3(32, 8)>>>(Wd, Wh);
    gemm_mma_kernel<<<dim3(NPAD / BN, ROWS / BM), 256, DYN_SMEM>>>(bd, bh, Wc);
    broadcast_add_kernel<<<ROWS / BCAST_ROWS, 256>>>(bc, out);
}